// round 9
// baseline (speedup 1.0000x reference)
#include <cuda_runtime.h>
#include <cstdint>

#define NXG    512
#define NYG    512
#define NCELL  (NXG * NYG)   // 262144
#define MAXB   8             // scratch sized for up to 8 batches
#define CCHUNK 16            // channels per block (C=64 -> 4 chunks) [R5/R7 optimum]

// Inverse map cell -> (global pillar index + 1), 0 = empty.
// NEVER zeroed at runtime: entries are validated against current inputs in
// bev_write (stale entries are rejected or provably identical to what this
// call writes). Zero-initialized at module load.
__device__ unsigned short g_inv16[MAXB * NCELL];
__device__ int            g_inv32[MAXB * NCELL];

// ---------------------------------------------------------------------------
template <typename T>
__global__ void build_inv_kernel(const int* __restrict__ coords,
                                 const int* __restrict__ mask,
                                 T* __restrict__ inv,
                                 int BP, int P)
{
    int bp = blockIdx.x * blockDim.x + threadIdx.x;
    if (bp < BP && mask[bp] > 0) {
        int ix = coords[2 * bp + 0];
        int iy = coords[2 * bp + 1];
        int b  = bp / P;
        inv[b * NCELL + iy * NXG + ix] = (T)(bp + 1);
    }
#if __CUDA_ARCH__ >= 900
    cudaTriggerProgrammaticLaunchCompletion();
#endif
}

// ---------------------------------------------------------------------------
// Validate an inv entry against CURRENT inputs. Returns emb row ptr or null.
__device__ __forceinline__
const float* validate(int v, int cell, int b,
                      const float* __restrict__ emb,
                      const int*   __restrict__ coords,
                      const int*   __restrict__ mask,
                      int BP, int P, int C, int c0)
{
    if (v == 0) return nullptr;
    int bp = v - 1;
    if (bp >= BP) return nullptr;
    if (bp / P != b) return nullptr;
    if (mask[bp] <= 0) return nullptr;
    int ix = coords[2 * bp + 0];
    int iy = coords[2 * bp + 1];
    if ((iy * NXG + ix) != cell) return nullptr;
    return emb + (long long)bp * C + c0;
}

// ---------------------------------------------------------------------------
// Kernel C: write full BEV output as coalesced float4 streaming stores.
// grid = (NCELL/1024, C/CCHUNK, B). 4 cells/thread, CCHUNK channel planes.
// Launched with PDL: waits on build_inv only at the inv read.
template <typename T>
__global__ void __launch_bounds__(256)
bev_write_kernel(const float* __restrict__ emb,
                 const int*   __restrict__ coords,
                 const int*   __restrict__ mask,
                 const T*     __restrict__ inv,
                 float*       __restrict__ out,
                 int BP, int P, int C)
{
    int b        = blockIdx.z;
    int c0       = blockIdx.y * CCHUNK;
    int cellBase = (blockIdx.x * 256 + threadIdx.x) * 4;   // 4 cells per thread

    float* obase = out + ((long long)b * C + c0) * NCELL + cellBase;

#if __CUDA_ARCH__ >= 900
    cudaGridDependencySynchronize();   // build_inv results must be visible
#endif

    int v0, v1, v2, v3;
    if (sizeof(T) == 2) {
        const ushort4 pi = *(const ushort4*)(&inv[b * NCELL + cellBase]);
        v0 = pi.x; v1 = pi.y; v2 = pi.z; v3 = pi.w;
    } else {
        const int4 pi = *(const int4*)(&inv[b * NCELL + cellBase]);
        v0 = pi.x; v1 = pi.y; v2 = pi.z; v3 = pi.w;
    }

    const float* e0 = validate(v0, cellBase + 0, b, emb, coords, mask, BP, P, C, c0);
    const float* e1 = validate(v1, cellBase + 1, b, emb, coords, mask, BP, P, C, c0);
    const float* e2 = validate(v2, cellBase + 2, b, emb, coords, mask, BP, P, C, c0);
    const float* e3 = validate(v3, cellBase + 3, b, emb, coords, mask, BP, P, C, c0);

    #pragma unroll
    for (int c = 0; c < CCHUNK; c++) {
        float4 v;
        v.x = e0 ? e0[c] : 0.0f;
        v.y = e1 ? e1[c] : 0.0f;
        v.z = e2 ? e2[c] : 0.0f;
        v.w = e3 ? e3[c] : 0.0f;
        __stcs((float4*)(obase + (long long)c * NCELL), v);
    }
}

// ---------------------------------------------------------------------------
template <typename T>
static void launch_path(const float* emb, const int* coords, const int* mask,
                        T* inv, float* out, int BP, int P, int C, int B)
{
    int threads = 256;
    int bblocks = (BP + threads - 1) / threads;
    build_inv_kernel<T><<<bblocks, threads>>>(coords, mask, inv, BP, P);

    // bev_write with programmatic dependent launch: overlaps with build_inv tail
    cudaLaunchAttribute attr[1];
    attr[0].id = cudaLaunchAttributeProgrammaticStreamSerialization;
    attr[0].val.programmaticStreamSerializationAllowed = 1;

    cudaLaunchConfig_t cfg = {};
    cfg.gridDim  = dim3(NCELL / 1024, C / CCHUNK, B);
    cfg.blockDim = dim3(256, 1, 1);
    cfg.dynamicSmemBytes = 0;
    cfg.stream   = 0;
    cfg.attrs    = attr;
    cfg.numAttrs = 1;

    cudaError_t err = cudaLaunchKernelEx(&cfg, bev_write_kernel<T>,
                                         emb, coords, mask, (const T*)inv, out, BP, P, C);
    if (err != cudaSuccess) {
        // fallback: plain serialized launch
        bev_write_kernel<T><<<cfg.gridDim, cfg.blockDim>>>(emb, coords, mask,
                                                           (const T*)inv, out, BP, P, C);
    }
}

extern "C" void kernel_launch(void* const* d_in, const int* in_sizes, int n_in,
                              void* d_out, int out_size)
{
    const float* emb    = (const float*)d_in[0];   // [B, P, C] f32
    const int*   coords = (const int*)  d_in[1];   // [B, P, 2] i32
    const int*   mask   = (const int*)  d_in[2];   // [B, P]    i32

    int BP = in_sizes[2];                 // B*P
    int C  = in_sizes[0] / BP;            // 64
    int B  = out_size / (C * NCELL);      // 4
    int P  = BP / B;

    float* out = (float*)d_out;

    if (BP + 1 <= 65535) {
        unsigned short* inv = nullptr;
        cudaGetSymbolAddress((void**)&inv, g_inv16);
        launch_path<unsigned short>(emb, coords, mask, inv, out, BP, P, C, B);
    } else {
        int* inv = nullptr;
        cudaGetSymbolAddress((void**)&inv, g_inv32);
        launch_path<int>(emb, coords, mask, inv, out, BP, P, C, B);
    }
}

// round 10
// speedup vs baseline: 1.0307x; 1.0307x over previous
#include <cuda_runtime.h>
#include <cstdint>

#define NXG    512
#define NYG    512
#define NCELL  (NXG * NYG)   // 262144
#define MAXB   8             // scratch sized for up to 8 batches
#define CCHUNK 8             // channels per block (R8-proven best wall-clock)

// Inverse map cell -> (global pillar index + 1), 0 = empty.
// NEVER zeroed at runtime: entries are validated against current inputs in
// bev_write (stale entries are rejected or provably identical to what this
// call writes). Zero-initialized at module load.
__device__ unsigned short g_inv16[MAXB * NCELL];
__device__ int            g_inv32[MAXB * NCELL];

// ---------------------------------------------------------------------------
template <typename T>
__global__ void build_inv_kernel(const int* __restrict__ coords,
                                 const int* __restrict__ mask,
                                 T* __restrict__ inv,
                                 int BP, int P)
{
    int bp = blockIdx.x * blockDim.x + threadIdx.x;
    if (bp < BP && mask[bp] > 0) {
        int2 cc = ((const int2*)coords)[bp];
        int b  = bp / P;
        inv[b * NCELL + cc.y * NXG + cc.x] = (T)(bp + 1);
    }
#if __CUDA_ARCH__ >= 900
    cudaTriggerProgrammaticLaunchCompletion();
#endif
}

// ---------------------------------------------------------------------------
// Validate an inv entry against CURRENT inputs. Returns emb row ptr or null.
template <int CT>
__device__ __forceinline__
const float* validate(int v, int cell, int b,
                      const float* __restrict__ emb,
                      const int*   __restrict__ coords,
                      const int*   __restrict__ mask,
                      int BP, int P, int C, int c0)
{
    if (v == 0) return nullptr;
    int bp = v - 1;
    if (bp >= BP) return nullptr;
    if (bp / P != b) return nullptr;
    if (mask[bp] <= 0) return nullptr;
    int2 cc = ((const int2*)coords)[bp];
    if ((cc.y * NXG + cc.x) != cell) return nullptr;
    int cs = (CT > 0) ? CT : C;
    return emb + (long long)bp * cs + c0;
}

// ---------------------------------------------------------------------------
// Kernel C: write full BEV output as coalesced float4 streaming stores.
// grid = (NCELL/1024, C/CCHUNK, B). 4 cells/thread, CCHUNK channel planes.
// Launched with PDL: waits on build_inv only at the inv read.
// CT: compile-time channel count (0 = use runtime C).
template <typename T, int CT>
__global__ void __launch_bounds__(256)
bev_write_kernel(const float* __restrict__ emb,
                 const int*   __restrict__ coords,
                 const int*   __restrict__ mask,
                 const T*     __restrict__ inv,
                 float*       __restrict__ out,
                 int BP, int P, int C)
{
    const int cs = (CT > 0) ? CT : C;
    int b        = blockIdx.z;
    int c0       = blockIdx.y * CCHUNK;
    int cellBase = (blockIdx.x * 256 + threadIdx.x) * 4;   // 4 cells per thread

    float* obase = out + ((long long)b * cs + c0) * NCELL + cellBase;

#if __CUDA_ARCH__ >= 900
    cudaGridDependencySynchronize();   // build_inv results must be visible
#endif

    int v0, v1, v2, v3;
    if (sizeof(T) == 2) {
        const ushort4 pi = *(const ushort4*)(&inv[b * NCELL + cellBase]);
        v0 = pi.x; v1 = pi.y; v2 = pi.z; v3 = pi.w;
    } else {
        const int4 pi = *(const int4*)(&inv[b * NCELL + cellBase]);
        v0 = pi.x; v1 = pi.y; v2 = pi.z; v3 = pi.w;
    }

    const float* e0 = validate<CT>(v0, cellBase + 0, b, emb, coords, mask, BP, P, C, c0);
    const float* e1 = validate<CT>(v1, cellBase + 1, b, emb, coords, mask, BP, P, C, c0);
    const float* e2 = validate<CT>(v2, cellBase + 2, b, emb, coords, mask, BP, P, C, c0);
    const float* e3 = validate<CT>(v3, cellBase + 3, b, emb, coords, mask, BP, P, C, c0);

    #pragma unroll
    for (int c = 0; c < CCHUNK; c++) {
        float4 v;
        v.x = e0 ? e0[c] : 0.0f;
        v.y = e1 ? e1[c] : 0.0f;
        v.z = e2 ? e2[c] : 0.0f;
        v.w = e3 ? e3[c] : 0.0f;
        __stcs((float4*)(obase + (long long)c * NCELL), v);
    }
}

// ---------------------------------------------------------------------------
template <typename T, int CT>
static void launch_bev(const float* emb, const int* coords, const int* mask,
                       T* inv, float* out, int BP, int P, int C, int B)
{
    cudaLaunchAttribute attr[1];
    attr[0].id = cudaLaunchAttributeProgrammaticStreamSerialization;
    attr[0].val.programmaticStreamSerializationAllowed = 1;

    cudaLaunchConfig_t cfg = {};
    cfg.gridDim  = dim3(NCELL / 1024, C / CCHUNK, B);
    cfg.blockDim = dim3(256, 1, 1);
    cfg.dynamicSmemBytes = 0;
    cfg.stream   = 0;
    cfg.attrs    = attr;
    cfg.numAttrs = 1;

    cudaError_t err = cudaLaunchKernelEx(&cfg, bev_write_kernel<T, CT>,
                                         emb, coords, mask, (const T*)inv, out, BP, P, C);
    if (err != cudaSuccess) {
        bev_write_kernel<T, CT><<<cfg.gridDim, cfg.blockDim>>>(emb, coords, mask,
                                                               (const T*)inv, out, BP, P, C);
    }
}

template <typename T>
static void launch_path(const float* emb, const int* coords, const int* mask,
                        T* inv, float* out, int BP, int P, int C, int B)
{
    int threads = 256;
    int bblocks = (BP + threads - 1) / threads;
    build_inv_kernel<T><<<bblocks, threads>>>(coords, mask, inv, BP, P);

    if (C == 64) launch_bev<T, 64>(emb, coords, mask, inv, out, BP, P, C, B);
    else         launch_bev<T, 0 >(emb, coords, mask, inv, out, BP, P, C, B);
}

extern "C" void kernel_launch(void* const* d_in, const int* in_sizes, int n_in,
                              void* d_out, int out_size)
{
    const float* emb    = (const float*)d_in[0];   // [B, P, C] f32
    const int*   coords = (const int*)  d_in[1];   // [B, P, 2] i32
    const int*   mask   = (const int*)  d_in[2];   // [B, P]    i32

    int BP = in_sizes[2];                 // B*P
    int C  = in_sizes[0] / BP;            // 64
    int B  = out_size / (C * NCELL);      // 4
    int P  = BP / B;

    float* out = (float*)d_out;

    if (BP + 1 <= 65535) {
        unsigned short* inv = nullptr;
        cudaGetSymbolAddress((void**)&inv, g_inv16);
        launch_path<unsigned short>(emb, coords, mask, inv, out, BP, P, C, B);
    } else {
        int* inv = nullptr;
        cudaGetSymbolAddress((void**)&inv, g_inv32);
        launch_path<int>(emb, coords, mask, inv, out, BP, P, C, B);
    }
}